// round 1
// baseline (speedup 1.0000x reference)
#include <cuda_runtime.h>

// out[b, h, w] = 0.5f * (x[b,0,h,w] + x[b,1,h,w] + x[b,2,h,w])
// x: (16, 3, 1024, 1024) f32, out: (16, 1, 1024, 1024) f32.
// Pure HBM-bound streaming reduction; float4 vectorized.

static constexpr int B = 16;
static constexpr int C = 3;
static constexpr int HW = 1024 * 1024;
static constexpr int HW4 = HW / 4;          // float4 elements per plane (2^18)
static constexpr int NOUT4 = B * HW4;       // total float4 outputs (4M)

__global__ __launch_bounds__(256) void haar_sum_kernel(
    const float4* __restrict__ in, float4* __restrict__ out)
{
    int j = blockIdx.x * blockDim.x + threadIdx.x;
    if (j >= NOUT4) return;

    int b = j >> 18;            // j / HW4
    int p = j & (HW4 - 1);      // j % HW4
    const float4* base = in + (size_t)b * (C * HW4) + p;

    float4 a = base[0];
    float4 c1 = base[HW4];
    float4 c2 = base[2 * HW4];

    float4 r;
    r.x = 0.5f * (a.x + c1.x + c2.x);
    r.y = 0.5f * (a.y + c1.y + c2.y);
    r.z = 0.5f * (a.z + c1.z + c2.z);
    r.w = 0.5f * (a.w + c1.w + c2.w);

    out[j] = r;
}

extern "C" void kernel_launch(void* const* d_in, const int* in_sizes, int n_in,
                              void* d_out, int out_size)
{
    const float4* in = (const float4*)d_in[0];
    float4* out = (float4*)d_out;

    int threads = 256;
    int blocks = (NOUT4 + threads - 1) / threads;   // 16384
    haar_sum_kernel<<<blocks, threads>>>(in, out);
}

// round 6
// speedup vs baseline: 1.0258x; 1.0258x over previous
#include <cuda_runtime.h>

// out[b, h, w] = 0.5f * (x[b,0,h,w] + x[b,1,h,w] + x[b,2,h,w])
// x: (16, 3, 1024, 1024) f32, out: (16, 1, 1024, 1024) f32.
// HBM-bound streaming reduction. R2: 2 float4 outputs per thread (6 independent
// LDG.128 front-batched -> deeper L1tex MLP) + streaming cache hints (.cs)
// since the 256MB footprint has zero reuse in the 126MB L2.

static constexpr int B = 16;
static constexpr int C = 3;
static constexpr int HW = 1024 * 1024;
static constexpr int HW4 = HW / 4;          // float4 per plane = 2^18
static constexpr int NOUT4 = B * HW4;       // 4M float4 outputs
static constexpr int TPB = 256;
static constexpr int PER_BLOCK = TPB * 2;   // 512 float4 per block

__global__ __launch_bounds__(TPB) void haar_sum_kernel(
    const float4* __restrict__ in, float4* __restrict__ out)
{
    int j0 = blockIdx.x * PER_BLOCK + threadIdx.x;   // first float4 index
    int j1 = j0 + TPB;                                // second, same b (512 | 2^18)

    int b = j0 >> 18;                                 // whole block in one batch
    const float4* base = in + (size_t)b * (C * HW4);
    int p0 = j0 & (HW4 - 1);
    int p1 = j1 & (HW4 - 1);

    // 6 independent streaming loads issued up front
    float4 a0 = __ldcs(base + p0);
    float4 a1 = __ldcs(base + p1);
    float4 b0 = __ldcs(base + HW4 + p0);
    float4 b1 = __ldcs(base + HW4 + p1);
    float4 c0 = __ldcs(base + 2 * HW4 + p0);
    float4 c1 = __ldcs(base + 2 * HW4 + p1);

    float4 r0, r1;
    r0.x = 0.5f * (a0.x + b0.x + c0.x);
    r0.y = 0.5f * (a0.y + b0.y + c0.y);
    r0.z = 0.5f * (a0.z + b0.z + c0.z);
    r0.w = 0.5f * (a0.w + b0.w + c0.w);
    r1.x = 0.5f * (a1.x + b1.x + c1.x);
    r1.y = 0.5f * (a1.y + b1.y + c1.y);
    r1.z = 0.5f * (a1.z + b1.z + c1.z);
    r1.w = 0.5f * (a1.w + b1.w + c1.w);

    __stcs(out + j0, r0);
    __stcs(out + j1, r1);
}

extern "C" void kernel_launch(void* const* d_in, const int* in_sizes, int n_in,
                              void* d_out, int out_size)
{
    const float4* in = (const float4*)d_in[0];
    float4* out = (float4*)d_out;

    int blocks = NOUT4 / PER_BLOCK;   // 8192, exact
    haar_sum_kernel<<<blocks, TPB>>>(in, out);
}